// round 16
// baseline (speedup 1.0000x reference)
#include <cuda_runtime.h>
#include <cuda_fp16.h>

#define N_NODES 100000
#define N_EDGES 1600000
#define CH 128
#define NGRAPH 512
#define RDIM 64
#define BN_EPS 1e-5f
#define NBINS 128

#define SCAN_BLK 256
#define NBLK ((N_NODES + SCAN_BLK - 1) / SCAN_BLK)   // 391

// ---------------- scratch (static device globals; no allocation) ----------------
__device__ int   g_is64;
__device__ int   g_ebase;
__device__ float g_deg[N_NODES];
__device__ float g_dinv[N_NODES];
__device__ int   g_ecnt[N_NODES];
__device__ int   g_off[N_NODES];
__device__ int   g_cursor[N_NODES];
__device__ int   g_order[N_NODES];      // degree-sorted node order
__device__ int   g_dhist[NBINS];
__device__ int   g_dbase[NBINS];
__device__ int   g_dcur[NBINS];
__device__ __align__(16) int2 g_csr[N_EDGES];                  // (src, weight-as-int)
__device__ __align__(256) __half g_h[(size_t)N_NODES * CH];    // fp16 messages
__device__ __align__(256) __half g_agg[(size_t)N_NODES * CH];  // conv output (fp16)
__device__ float g_bnsum[CH];
__device__ float g_bnsq[CH];
__device__ float g_counts[NGRAPH];
__device__ int   g_gstart[NGRAPH];

// index load that works for both int32 and int64 input buffers
__device__ __forceinline__ int load_idx(const void* p, size_t i) {
    if (g_is64) return (int)((const long long*)p)[i];
    return ((const int*)p)[i];
}

// ---------------- helpers ----------------
__device__ __forceinline__ int block_scan_excl(int v, int& block_total) {
    __shared__ int warp_sums[32];
    int lane = threadIdx.x & 31, wid = threadIdx.x >> 5;
    int inc = v;
#pragma unroll
    for (int o = 1; o < 32; o <<= 1) {
        int n = __shfl_up_sync(0xffffffffu, inc, o);
        if (lane >= o) inc += n;
    }
    if (lane == 31) warp_sums[wid] = inc;
    __syncthreads();
    int nw = blockDim.x >> 5;
    if (wid == 0) {
        int w = (lane < nw) ? warp_sums[lane] : 0;
#pragma unroll
        for (int o = 1; o < 32; o <<= 1) {
            int n = __shfl_up_sync(0xffffffffu, w, o);
            if (lane >= o) w += n;
        }
        if (lane < nw) warp_sums[lane] = w;
    }
    __syncthreads();
    int warp_off = (wid > 0) ? warp_sums[wid - 1] : 0;
    block_total = warp_sums[nw - 1];
    return warp_off + inc - v;
}

__device__ __forceinline__ unsigned f2tf32(float f) {
    unsigned r;
    asm("cvt.rna.tf32.f32 %0, %1;" : "=r"(r) : "f"(f));
    return r;
}

__device__ __forceinline__ void mma_tf32(float& d0, float& d1, float& d2, float& d3,
                                         unsigned a0, unsigned a1, unsigned a2, unsigned a3,
                                         unsigned b0, unsigned b1) {
    asm volatile(
        "mma.sync.aligned.m16n8k8.row.col.f32.tf32.tf32.f32 "
        "{%0,%1,%2,%3},{%4,%5,%6,%7},{%8,%9},{%0,%1,%2,%3};"
        : "+f"(d0), "+f"(d1), "+f"(d2), "+f"(d3)
        : "r"(a0), "r"(a1), "r"(a2), "r"(a3), "r"(b0), "r"(b1));
}

// ---------------- setup kernels ----------------
__global__ void init_kernel(const int* __restrict__ ei32) {
    int i = blockIdx.x * blockDim.x + threadIdx.x;
    if (i == 0) {
        g_is64 = (ei32[1] == 0 && ei32[3] == 0 && ei32[5] == 0 && ei32[7] == 0) ? 1 : 0;
        g_ebase = 0;
    }
    if (i < N_NODES) { g_deg[i] = 1.0f; g_cursor[i] = 0; }
    if (i < NGRAPH)  g_counts[i] = 0.0f;
    if (i < CH) { g_bnsum[i] = 0.0f; g_bnsq[i] = 0.0f; g_dhist[i] = 0; g_dcur[i] = 0; }
}

__global__ void deg_kernel(const void* __restrict__ ei, const void* __restrict__ batch) {
    int e = blockIdx.x * blockDim.x + threadIdx.x;
    if (e < N_EDGES) {
        int d = load_idx(ei, (size_t)N_EDGES + e);
        if (d >= 0 && d < N_NODES) atomicAdd(&g_deg[d], 1.0f);
    }
    if (e < N_NODES) {
        int b = load_idx(batch, e);
        if (b >= 0 && b < NGRAPH) atomicAdd(&g_counts[b], 1.0f);
    }
}

// per-block prefix + atomic base (CSR ranges only need disjointness) + deg histogram
__global__ void scan1_kernel() {
    __shared__ int sbase;
    int i = blockIdx.x * SCAN_BLK + threadIdx.x;
    int v = 0;
    if (i < N_NODES) {
        float dg = g_deg[i];
        v = (int)dg - 1;
        g_ecnt[i] = v;
        g_dinv[i] = rsqrtf(dg);
        atomicAdd(&g_dhist[min(v, NBINS - 1)], 1);
    }
    int tot;
    int e = block_scan_excl(v, tot);
    if (threadIdx.x == 0) sbase = atomicAdd(&g_ebase, tot);
    __syncthreads();
    if (i < N_NODES) g_off[i] = sbase + e;
}

// 1-block prefix over the degree histogram (stream2, hidden)
__global__ void dscan_kernel() {
    int t = threadIdx.x;
    int v = g_dhist[t];
    int tot;
    int e = block_scan_excl(v, tot);
    g_dbase[t] = e;
}

// scatter nodes into degree-sorted order (stream2, hidden)
__global__ void order_kernel() {
    int i = blockIdx.x * blockDim.x + threadIdx.x;
    if (i >= N_NODES) return;
    int bin = min(g_ecnt[i], NBINS - 1);
    int pos = g_dbase[bin] + atomicAdd(&g_dcur[bin], 1);
    g_order[pos] = i;
}

// graph-range scan (true order needed); stream2, hidden
__global__ void gscan_kernel() {   // one block, NGRAPH threads
    int t = threadIdx.x;
    int v = (int)g_counts[t];
    int tot;
    int e = block_scan_excl(v, tot);
    g_gstart[t] = e;
}

__global__ void scatter_kernel(const void* __restrict__ ei) {
    int e = blockIdx.x * blockDim.x + threadIdx.x;
    if (e >= N_EDGES) return;
    int s = load_idx(ei, e);
    int d = load_idx(ei, (size_t)N_EDGES + e);
    if (s < 0 || s >= N_NODES || d < 0 || d >= N_NODES) return;
    int pos = g_off[d] + atomicAdd(&g_cursor[d], 1);
    if (pos >= 0 && pos < N_EDGES) {
        float w = g_dinv[s] * g_dinv[d];
        g_csr[pos] = make_int2(s, __float_as_int(w));
    }
}

// ---------------- tensor-core GEMM (tf32): g_h = fp16(in @ W) -------------------
// TRANS=true: input is fp16 g_agg; BN scale/shift computed in-kernel from
// g_bnsum/g_bnsq and applied with ReLU on load.
template <bool TRANS>
__global__ __launch_bounds__(256) void gemm_tc_kernel(
    const float* __restrict__ Xext, const float* __restrict__ W,
    const float* __restrict__ gamma, const float* __restrict__ beta)
{
    __shared__ unsigned Bs[64][136];
    __shared__ float Sc[CH], Sh[CH];

    int tid = threadIdx.x;
    int lane = tid & 31, warp = tid >> 5;
    int gid = lane >> 2, tig = lane & 3;
    int row0 = blockIdx.x * 128 + warp * 16;
    int r0 = row0 + gid, r1 = r0 + 8;
    bool val0 = r0 < N_NODES, val1 = r1 < N_NODES;

    if (TRANS && tid < CH) {
        float inv_n = 1.0f / (float)N_NODES;
        float mu = g_bnsum[tid] * inv_n;
        float var = g_bnsq[tid] * inv_n - mu * mu;
        float rstd = rsqrtf(var + BN_EPS);
        float sc = gamma[tid] * rstd;
        Sc[tid] = sc;
        Sh[tid] = beta[tid] - mu * sc;
    }

    float acc[16][4];
#pragma unroll
    for (int nt = 0; nt < 16; nt++)
#pragma unroll
        for (int j = 0; j < 4; j++) acc[nt][j] = 0.0f;

    for (int p = 0; p < 2; p++) {
        for (int i = tid; i < 64 * 128; i += 256) {
            int k = i >> 7, n = i & 127;
            Bs[k][n] = f2tf32(W[(size_t)(p * 64 + k) * CH + n]);
        }
        __syncthreads();

        for (int k0 = 0; k0 < 64; k0 += 8) {
            int kg = p * 64 + k0;
            float a0f, a1f, a2f, a3f;
            if (TRANS) {
                a0f = val0 ? __half2float(g_agg[(size_t)r0 * CH + kg + tig])     : 0.0f;
                a1f = val1 ? __half2float(g_agg[(size_t)r1 * CH + kg + tig])     : 0.0f;
                a2f = val0 ? __half2float(g_agg[(size_t)r0 * CH + kg + tig + 4]) : 0.0f;
                a3f = val1 ? __half2float(g_agg[(size_t)r1 * CH + kg + tig + 4]) : 0.0f;
                float sc0 = Sc[kg + tig],     sh0 = Sh[kg + tig];
                float sc1 = Sc[kg + tig + 4], sh1 = Sh[kg + tig + 4];
                a0f = fmaxf(fmaf(sc0, a0f, sh0), 0.0f);
                a1f = fmaxf(fmaf(sc0, a1f, sh0), 0.0f);
                a2f = fmaxf(fmaf(sc1, a2f, sh1), 0.0f);
                a3f = fmaxf(fmaf(sc1, a3f, sh1), 0.0f);
            } else {
                a0f = val0 ? Xext[(size_t)r0 * CH + kg + tig]     : 0.0f;
                a1f = val1 ? Xext[(size_t)r1 * CH + kg + tig]     : 0.0f;
                a2f = val0 ? Xext[(size_t)r0 * CH + kg + tig + 4] : 0.0f;
                a3f = val1 ? Xext[(size_t)r1 * CH + kg + tig + 4] : 0.0f;
            }
            unsigned a0 = f2tf32(a0f), a1 = f2tf32(a1f);
            unsigned a2 = f2tf32(a2f), a3 = f2tf32(a3f);
#pragma unroll
            for (int nt = 0; nt < 16; nt++) {
                unsigned b0 = Bs[k0 + tig][nt * 8 + gid];
                unsigned b1 = Bs[k0 + tig + 4][nt * 8 + gid];
                mma_tf32(acc[nt][0], acc[nt][1], acc[nt][2], acc[nt][3],
                         a0, a1, a2, a3, b0, b1);
            }
        }
        __syncthreads();
    }

#pragma unroll
    for (int nt = 0; nt < 16; nt++) {
        int c = nt * 8 + tig * 2;
        if (val0) {
            *(__half2*)&g_h[(size_t)r0 * CH + c] =
                __float22half2_rn(make_float2(acc[nt][0], acc[nt][1]));
        }
        if (val1) {
            *(__half2*)&g_h[(size_t)r1 * CH + c] =
                __float22half2_rn(make_float2(acc[nt][2], acc[nt][3]));
        }
    }
}

// ---------------- edge aggregation: warp per dst node (degree-sorted order) ------
// Proven r8/r11 loop: 8-edge batches, one LDG.64 (int2) per lane, dual accs.
// Nodes assigned via g_order so warps in a block have near-equal degree.
__global__ __launch_bounds__(256) void agg_kernel(const float* __restrict__ bias) {
    int gw = (blockIdx.x * 256 + threadIdx.x) >> 5;
    if (gw >= N_NODES) return;
    int node = g_order[gw];
    int lane = threadIdx.x & 31;
    int start = g_off[node];
    int cnt = g_ecnt[node];
    int c0 = lane << 2;

    float dv = g_dinv[node];
    float d2 = dv * dv;
    uint2 sh_ = *(const uint2*)&g_h[(size_t)node * CH + c0];
    float2 s01 = __half22float2(*(__half2*)&sh_.x);
    float2 s23 = __half22float2(*(__half2*)&sh_.y);
    float4 acc = make_float4(fmaf(s01.x, d2, bias[c0]),
                             fmaf(s01.y, d2, bias[c0 + 1]),
                             fmaf(s23.x, d2, bias[c0 + 2]),
                             fmaf(s23.y, d2, bias[c0 + 3]));
    float4 acc2 = make_float4(0.0f, 0.0f, 0.0f, 0.0f);

    int sub = lane & 7;
    for (int e = 0; e < cnt; e += 8) {
        int myE = e + sub;
        int2 sw = make_int2(0, 0);
        if (myE < cnt) sw = g_csr[start + myE];
        int   s = sw.x;
        float w = __int_as_float(sw.y);
#pragma unroll
        for (int i = 0; i < 8; i++) {
            int   si = __shfl_sync(0xffffffffu, s, i);
            float wi = __shfl_sync(0xffffffffu, w, i);
            uint2 hv = *(const uint2*)&g_h[(size_t)si * CH + c0];
            float2 v01 = __half22float2(*(__half2*)&hv.x);
            float2 v23 = __half22float2(*(__half2*)&hv.y);
            if (i & 1) {
                acc2.x = fmaf(wi, v01.x, acc2.x); acc2.y = fmaf(wi, v01.y, acc2.y);
                acc2.z = fmaf(wi, v23.x, acc2.z); acc2.w = fmaf(wi, v23.y, acc2.w);
            } else {
                acc.x = fmaf(wi, v01.x, acc.x); acc.y = fmaf(wi, v01.y, acc.y);
                acc.z = fmaf(wi, v23.x, acc.z); acc.w = fmaf(wi, v23.y, acc.w);
            }
        }
    }
    acc.x += acc2.x; acc.y += acc2.y; acc.z += acc2.z; acc.w += acc2.w;
    __half2 h01 = __float22half2_rn(make_float2(acc.x, acc.y));
    __half2 h23 = __float22half2_rn(make_float2(acc.z, acc.w));
    uint2 st;
    st.x = *(unsigned*)&h01;
    st.y = *(unsigned*)&h23;
    *(uint2*)&g_agg[(size_t)node * CH + c0] = st;
}

// ---------------- BatchNorm statistics ----------------
__global__ __launch_bounds__(256) void bnstats_kernel() {
    int c = threadIdx.x & 127;
    int half_ = threadIdx.x >> 7;
    int r0 = blockIdx.x * 512 + half_;
    float s = 0.0f, q = 0.0f;
    for (int i = 0; i < 512; i += 2) {
        int r = r0 + i;
        if (r < N_NODES) {
            float v = __half2float(g_agg[(size_t)r * CH + c]);
            s += v;
            q = fmaf(v, v, q);
        }
    }
    atomicAdd(&g_bnsum[c], s);
    atomicAdd(&g_bnsq[c], q);
}

// ---------------- pooled mean + MLP head, one block per graph ----------------
__global__ __launch_bounds__(128) void final_kernel(
    const float* __restrict__ rst,
    const float* __restrict__ Wg, const float* __restrict__ bg,
    const float* __restrict__ Wr, const float* __restrict__ br,
    const float* __restrict__ Wc, const float* __restrict__ bc,
    float* __restrict__ out)
{
    __shared__ float p[CH];
    __shared__ float rv[RDIM];
    __shared__ float comb[CH];
    int g = blockIdx.x;
    int t = threadIdx.x;
    float cntf = g_counts[g];
    int start = g_gstart[g];
    int cnt = (int)cntf;
    float s = 0.0f;
    for (int i = 0; i < cnt; i++)
        s += __half2float(g_agg[(size_t)(start + i) * CH + t]);
    p[t] = s / fmaxf(cntf, 1.0f);
    if (t < RDIM) rv[t] = rst[g * RDIM + t];
    __syncthreads();
    if (t < 64) {
        float a = bg[t];
#pragma unroll 4
        for (int k = 0; k < 128; k++) a = fmaf(p[k], Wg[k * 64 + t], a);
        comb[t] = fmaxf(a, 0.0f);
    } else {
        int j = t - 64;
        float a = br[j];
#pragma unroll 4
        for (int k = 0; k < 64; k++) a = fmaf(rv[k], Wr[k * 64 + j], a);
        comb[64 + j] = fmaxf(a, 0.0f);
    }
    __syncthreads();
    if (t < 2) {
        float a = bc[t];
        for (int k = 0; k < 128; k++) a = fmaf(comb[k], Wc[k * 2 + t], a);
        out[g * 2 + t] = a;
    }
}

// ---------------- streams/events for overlap (created at load) -------------------
static cudaStream_t s_stream2;
static cudaEvent_t  s_ev_root, s_ev_gemm1, s_ev_scan1, s_ev_order, s_ev_gscan;
static struct StreamInit {
    StreamInit() {
        cudaStreamCreateWithFlags(&s_stream2, cudaStreamNonBlocking);
        cudaEventCreateWithFlags(&s_ev_root, cudaEventDisableTiming);
        cudaEventCreateWithFlags(&s_ev_gemm1, cudaEventDisableTiming);
        cudaEventCreateWithFlags(&s_ev_scan1, cudaEventDisableTiming);
        cudaEventCreateWithFlags(&s_ev_order, cudaEventDisableTiming);
        cudaEventCreateWithFlags(&s_ev_gscan, cudaEventDisableTiming);
    }
} s_streaminit;

// ---------------- launcher ----------------
extern "C" void kernel_launch(void* const* d_in, const int* in_sizes, int n_in,
                              void* d_out, int out_size) {
    const float* x     = (const float*)d_in[0];
    const void*  ei    = d_in[1];
    const void*  batch = d_in[2];
    const float* rst   = (const float*)d_in[3];
    int base = (n_in >= 17) ? 5 : 4;
    const float* W1    = (const float*)d_in[base + 0];
    const float* b1    = (const float*)d_in[base + 1];
    const float* gamma = (const float*)d_in[base + 2];
    const float* beta  = (const float*)d_in[base + 3];
    const float* W2    = (const float*)d_in[base + 4];
    const float* b2    = (const float*)d_in[base + 5];
    const float* Wg    = (const float*)d_in[base + 6];
    const float* bg    = (const float*)d_in[base + 7];
    const float* Wr    = (const float*)d_in[base + 8];
    const float* br    = (const float*)d_in[base + 9];
    const float* Wc    = (const float*)d_in[base + 10];
    const float* bc    = (const float*)d_in[base + 11];
    float* out = (float*)d_out;

    int nblk_nodes = (N_NODES + 255) / 256;
    int nblk_edges = (N_EDGES + 255) / 256;
    int gemm_blocks = (N_NODES + 127) / 128;          // 782
    int agg_blocks = (N_NODES * 32 + 255) / 256;      // 12500
    int bn_blocks = (N_NODES + 511) / 512;            // 196

    // fork: GEMM1 (independent of CSR build) on stream2
    cudaEventRecord(s_ev_root, 0);
    cudaStreamWaitEvent(s_stream2, s_ev_root, 0);
    gemm_tc_kernel<false><<<gemm_blocks, 256, 0, s_stream2>>>(x, W1, nullptr, nullptr);
    cudaEventRecord(s_ev_gemm1, s_stream2);

    // main stream: graph structure
    init_kernel<<<nblk_nodes, 256>>>((const int*)ei);
    deg_kernel<<<nblk_edges, 256>>>(ei, batch);
    scan1_kernel<<<NBLK, SCAN_BLK>>>();
    cudaEventRecord(s_ev_scan1, 0);
    scatter_kernel<<<nblk_edges, 256>>>(ei);

    // stream2 (after gemm1, in-order): degree sort + graph scan, hidden by scatter
    cudaStreamWaitEvent(s_stream2, s_ev_scan1, 0);
    dscan_kernel<<<1, NBINS, 0, s_stream2>>>();
    order_kernel<<<nblk_nodes, 256, 0, s_stream2>>>();
    cudaEventRecord(s_ev_order, s_stream2);
    gscan_kernel<<<1, NGRAPH, 0, s_stream2>>>();
    cudaEventRecord(s_ev_gscan, s_stream2);

    // join gemm1 + order, then layer-1 aggregation
    cudaStreamWaitEvent(0, s_ev_gemm1, 0);
    cudaStreamWaitEvent(0, s_ev_order, 0);
    agg_kernel<<<agg_blocks, 256>>>(b1);

    // BN stats (finalize fused into gemm2 prologue)
    bnstats_kernel<<<bn_blocks, 256>>>();

    // layer 2
    gemm_tc_kernel<true><<<gemm_blocks, 256>>>(nullptr, W2, gamma, beta);
    agg_kernel<<<agg_blocks, 256>>>(b2);

    // pooling + head (needs g_gstart from stream2)
    cudaStreamWaitEvent(0, s_ev_gscan, 0);
    final_kernel<<<NGRAPH, 128>>>(rst, Wg, bg, Wr, br, Wc, bc, out);
}

// round 17
// speedup vs baseline: 1.1596x; 1.1596x over previous
#include <cuda_runtime.h>
#include <cuda_fp16.h>

#define N_NODES 100000
#define N_EDGES 1600000
#define CH 128
#define NGRAPH 512
#define RDIM 64
#define BN_EPS 1e-5f

#define SCAN_BLK 256
#define NBLK ((N_NODES + SCAN_BLK - 1) / SCAN_BLK)   // 391

// ---------------- scratch (static device globals; no allocation) ----------------
__device__ int   g_is64;
__device__ float g_deg[N_NODES];
__device__ float g_dinv[N_NODES];
__device__ int   g_ecnt[N_NODES];
__device__ int   g_off[N_NODES];
__device__ int   g_cursor[N_NODES];
__device__ int   g_bsum[NBLK];
__device__ int   g_boff[NBLK];
__device__ __align__(16) int2 g_csr[N_EDGES];                 // (src, weight-as-int)
__device__ __align__(16) __half g_h[(size_t)N_NODES * CH];    // fp16 messages
__device__ __align__(16) __half g_agg[(size_t)N_NODES * CH];  // conv output (fp16)
__device__ float g_bnsum[CH];
__device__ float g_bnsq[CH];
__device__ float g_counts[NGRAPH];
__device__ int   g_gstart[NGRAPH];

// index load that works for both int32 and int64 input buffers
__device__ __forceinline__ int load_idx(const void* p, size_t i) {
    if (g_is64) return (int)((const long long*)p)[i];
    return ((const int*)p)[i];
}

// ---------------- helpers ----------------
__device__ __forceinline__ int block_scan_excl(int v, int& block_total) {
    __shared__ int warp_sums[32];
    int lane = threadIdx.x & 31, wid = threadIdx.x >> 5;
    int inc = v;
#pragma unroll
    for (int o = 1; o < 32; o <<= 1) {
        int n = __shfl_up_sync(0xffffffffu, inc, o);
        if (lane >= o) inc += n;
    }
    if (lane == 31) warp_sums[wid] = inc;
    __syncthreads();
    int nw = blockDim.x >> 5;
    if (wid == 0) {
        int w = (lane < nw) ? warp_sums[lane] : 0;
#pragma unroll
        for (int o = 1; o < 32; o <<= 1) {
            int n = __shfl_up_sync(0xffffffffu, w, o);
            if (lane >= o) w += n;
        }
        if (lane < nw) warp_sums[lane] = w;
    }
    __syncthreads();
    int warp_off = (wid > 0) ? warp_sums[wid - 1] : 0;
    block_total = warp_sums[nw - 1];
    return warp_off + inc - v;
}

__device__ __forceinline__ unsigned f2tf32(float f) {
    unsigned r;
    asm("cvt.rna.tf32.f32 %0, %1;" : "=r"(r) : "f"(f));
    return r;
}

__device__ __forceinline__ void mma_tf32(float& d0, float& d1, float& d2, float& d3,
                                         unsigned a0, unsigned a1, unsigned a2, unsigned a3,
                                         unsigned b0, unsigned b1) {
    asm volatile(
        "mma.sync.aligned.m16n8k8.row.col.f32.tf32.tf32.f32 "
        "{%0,%1,%2,%3},{%4,%5,%6,%7},{%8,%9},{%0,%1,%2,%3};"
        : "+f"(d0), "+f"(d1), "+f"(d2), "+f"(d3)
        : "r"(a0), "r"(a1), "r"(a2), "r"(a3), "r"(b0), "r"(b1));
}

// ---------------- setup kernels ----------------
__global__ void init_kernel(const int* __restrict__ ei32) {
    int i = blockIdx.x * blockDim.x + threadIdx.x;
    if (i == 0) {
        g_is64 = (ei32[1] == 0 && ei32[3] == 0 && ei32[5] == 0 && ei32[7] == 0) ? 1 : 0;
    }
    if (i < N_NODES) { g_deg[i] = 1.0f; g_cursor[i] = 0; }
    if (i < NGRAPH)  g_counts[i] = 0.0f;
    if (i < CH)      { g_bnsum[i] = 0.0f; g_bnsq[i] = 0.0f; }
}

__global__ void deg_kernel(const void* __restrict__ ei, const void* __restrict__ batch) {
    int e = blockIdx.x * blockDim.x + threadIdx.x;
    if (e < N_EDGES) {
        int d = load_idx(ei, (size_t)N_EDGES + e);
        if (d >= 0 && d < N_NODES) atomicAdd(&g_deg[d], 1.0f);
    }
    if (e < N_NODES) {
        int b = load_idx(batch, e);
        if (b >= 0 && b < NGRAPH) atomicAdd(&g_counts[b], 1.0f);
    }
}

__global__ void scan1_kernel() {
    int i = blockIdx.x * SCAN_BLK + threadIdx.x;
    int v = 0;
    if (i < N_NODES) {
        float dg = g_deg[i];
        v = (int)dg - 1;
        g_ecnt[i] = v;
        g_dinv[i] = rsqrtf(dg);
    }
    int tot;
    int e = block_scan_excl(v, tot);
    if (i < N_NODES) g_off[i] = e;
    if (threadIdx.x == 0) g_bsum[blockIdx.x] = tot;
}

__global__ void scan2_kernel() {   // one block, 512 threads: block scan + graph scan
    int t = threadIdx.x;
    int v = (t < NBLK) ? g_bsum[t] : 0;
    int tot;
    int e = block_scan_excl(v, tot);
    if (t < NBLK) g_boff[t] = e;
    __syncthreads();
    int v2 = (int)g_counts[t];
    int tot2;
    int e2 = block_scan_excl(v2, tot2);
    g_gstart[t] = e2;
}

__global__ void scatter_kernel(const void* __restrict__ ei) {
    int e = blockIdx.x * blockDim.x + threadIdx.x;
    if (e >= N_EDGES) return;
    int s = load_idx(ei, e);
    int d = load_idx(ei, (size_t)N_EDGES + e);
    if (s < 0 || s >= N_NODES || d < 0 || d >= N_NODES) return;
    int pos = g_off[d] + g_boff[d >> 8] + atomicAdd(&g_cursor[d], 1);
    if (pos >= 0 && pos < N_EDGES) {
        float w = g_dinv[s] * g_dinv[d];
        g_csr[pos] = make_int2(s, __float_as_int(w));
    }
}

// ---------------- tensor-core GEMM (tf32): g_h = fp16(in @ W) -------------------
// TRANS=true: input is fp16 g_agg; BN scale/shift computed in-kernel from
// g_bnsum/g_bnsq and applied with ReLU on load.
template <bool TRANS>
__global__ __launch_bounds__(256) void gemm_tc_kernel(
    const float* __restrict__ Xext, const float* __restrict__ W,
    const float* __restrict__ gamma, const float* __restrict__ beta)
{
    __shared__ unsigned Bs[64][136];
    __shared__ float Sc[CH], Sh[CH];

    int tid = threadIdx.x;
    int lane = tid & 31, warp = tid >> 5;
    int gid = lane >> 2, tig = lane & 3;
    int row0 = blockIdx.x * 128 + warp * 16;
    int r0 = row0 + gid, r1 = r0 + 8;
    bool val0 = r0 < N_NODES, val1 = r1 < N_NODES;

    if (TRANS && tid < CH) {
        float inv_n = 1.0f / (float)N_NODES;
        float mu = g_bnsum[tid] * inv_n;
        float var = g_bnsq[tid] * inv_n - mu * mu;
        float rstd = rsqrtf(var + BN_EPS);
        float sc = gamma[tid] * rstd;
        Sc[tid] = sc;
        Sh[tid] = beta[tid] - mu * sc;
    }

    float acc[16][4];
#pragma unroll
    for (int nt = 0; nt < 16; nt++)
#pragma unroll
        for (int j = 0; j < 4; j++) acc[nt][j] = 0.0f;

    for (int p = 0; p < 2; p++) {
        for (int i = tid; i < 64 * 128; i += 256) {
            int k = i >> 7, n = i & 127;
            Bs[k][n] = f2tf32(W[(size_t)(p * 64 + k) * CH + n]);
        }
        __syncthreads();

        for (int k0 = 0; k0 < 64; k0 += 8) {
            int kg = p * 64 + k0;
            float a0f, a1f, a2f, a3f;
            if (TRANS) {
                a0f = val0 ? __half2float(g_agg[(size_t)r0 * CH + kg + tig])     : 0.0f;
                a1f = val1 ? __half2float(g_agg[(size_t)r1 * CH + kg + tig])     : 0.0f;
                a2f = val0 ? __half2float(g_agg[(size_t)r0 * CH + kg + tig + 4]) : 0.0f;
                a3f = val1 ? __half2float(g_agg[(size_t)r1 * CH + kg + tig + 4]) : 0.0f;
                float sc0 = Sc[kg + tig],     sh0 = Sh[kg + tig];
                float sc1 = Sc[kg + tig + 4], sh1 = Sh[kg + tig + 4];
                a0f = fmaxf(fmaf(sc0, a0f, sh0), 0.0f);
                a1f = fmaxf(fmaf(sc0, a1f, sh0), 0.0f);
                a2f = fmaxf(fmaf(sc1, a2f, sh1), 0.0f);
                a3f = fmaxf(fmaf(sc1, a3f, sh1), 0.0f);
            } else {
                a0f = val0 ? Xext[(size_t)r0 * CH + kg + tig]     : 0.0f;
                a1f = val1 ? Xext[(size_t)r1 * CH + kg + tig]     : 0.0f;
                a2f = val0 ? Xext[(size_t)r0 * CH + kg + tig + 4] : 0.0f;
                a3f = val1 ? Xext[(size_t)r1 * CH + kg + tig + 4] : 0.0f;
            }
            unsigned a0 = f2tf32(a0f), a1 = f2tf32(a1f);
            unsigned a2 = f2tf32(a2f), a3 = f2tf32(a3f);
#pragma unroll
            for (int nt = 0; nt < 16; nt++) {
                unsigned b0 = Bs[k0 + tig][nt * 8 + gid];
                unsigned b1 = Bs[k0 + tig + 4][nt * 8 + gid];
                mma_tf32(acc[nt][0], acc[nt][1], acc[nt][2], acc[nt][3],
                         a0, a1, a2, a3, b0, b1);
            }
        }
        __syncthreads();
    }

#pragma unroll
    for (int nt = 0; nt < 16; nt++) {
        int c = nt * 8 + tig * 2;
        if (val0) {
            *(__half2*)&g_h[(size_t)r0 * CH + c] =
                __float22half2_rn(make_float2(acc[nt][0], acc[nt][1]));
        }
        if (val1) {
            *(__half2*)&g_h[(size_t)r1 * CH + c] =
                __float22half2_rn(make_float2(acc[nt][2], acc[nt][3]));
        }
    }
}

// ---------------- edge aggregation: warp per dst node, fp16 gathers --------------
// Proven loop: 8-edge batches, one LDG.64 (int2) per lane, dual accumulators.
// acc init = bias + dinv^2 * h_self; fp32 accumulation; fp16 store.
__global__ __launch_bounds__(256) void agg_kernel(const float* __restrict__ bias) {
    int node = (blockIdx.x * 256 + threadIdx.x) >> 5;
    if (node >= N_NODES) return;
    int lane = threadIdx.x & 31;
    int start = g_off[node] + g_boff[node >> 8];
    int cnt = g_ecnt[node];
    int c0 = lane << 2;

    float dv = g_dinv[node];
    float d2 = dv * dv;
    uint2 sh_ = *(const uint2*)&g_h[(size_t)node * CH + c0];
    float2 s01 = __half22float2(*(__half2*)&sh_.x);
    float2 s23 = __half22float2(*(__half2*)&sh_.y);
    float4 acc = make_float4(fmaf(s01.x, d2, bias[c0]),
                             fmaf(s01.y, d2, bias[c0 + 1]),
                             fmaf(s23.x, d2, bias[c0 + 2]),
                             fmaf(s23.y, d2, bias[c0 + 3]));
    float4 acc2 = make_float4(0.0f, 0.0f, 0.0f, 0.0f);

    int sub = lane & 7;
    for (int e = 0; e < cnt; e += 8) {
        int myE = e + sub;
        int2 sw = make_int2(0, 0);
        if (myE < cnt) sw = g_csr[start + myE];
        int   s = sw.x;
        float w = __int_as_float(sw.y);
#pragma unroll
        for (int i = 0; i < 8; i++) {
            int   si = __shfl_sync(0xffffffffu, s, i);
            float wi = __shfl_sync(0xffffffffu, w, i);
            uint2 hv = *(const uint2*)&g_h[(size_t)si * CH + c0];
            float2 v01 = __half22float2(*(__half2*)&hv.x);
            float2 v23 = __half22float2(*(__half2*)&hv.y);
            if (i & 1) {
                acc2.x = fmaf(wi, v01.x, acc2.x); acc2.y = fmaf(wi, v01.y, acc2.y);
                acc2.z = fmaf(wi, v23.x, acc2.z); acc2.w = fmaf(wi, v23.y, acc2.w);
            } else {
                acc.x = fmaf(wi, v01.x, acc.x); acc.y = fmaf(wi, v01.y, acc.y);
                acc.z = fmaf(wi, v23.x, acc.z); acc.w = fmaf(wi, v23.y, acc.w);
            }
        }
    }
    acc.x += acc2.x; acc.y += acc2.y; acc.z += acc2.z; acc.w += acc2.w;
    __half2 h01 = __float22half2_rn(make_float2(acc.x, acc.y));
    __half2 h23 = __float22half2_rn(make_float2(acc.z, acc.w));
    uint2 st;
    st.x = *(unsigned*)&h01;
    st.y = *(unsigned*)&h23;
    *(uint2*)&g_agg[(size_t)node * CH + c0] = st;
}

// ---------------- BatchNorm statistics ----------------
__global__ __launch_bounds__(256) void bnstats_kernel() {
    int c = threadIdx.x & 127;
    int half_ = threadIdx.x >> 7;
    int r0 = blockIdx.x * 512 + half_;
    float s = 0.0f, q = 0.0f;
    for (int i = 0; i < 512; i += 2) {
        int r = r0 + i;
        if (r < N_NODES) {
            float v = __half2float(g_agg[(size_t)r * CH + c]);
            s += v;
            q = fmaf(v, v, q);
        }
    }
    atomicAdd(&g_bnsum[c], s);
    atomicAdd(&g_bnsq[c], q);
}

// ---------------- pooled mean + MLP head, one block per graph ----------------
__global__ __launch_bounds__(128) void final_kernel(
    const float* __restrict__ rst,
    const float* __restrict__ Wg, const float* __restrict__ bg,
    const float* __restrict__ Wr, const float* __restrict__ br,
    const float* __restrict__ Wc, const float* __restrict__ bc,
    float* __restrict__ out)
{
    __shared__ float p[CH];
    __shared__ float rv[RDIM];
    __shared__ float comb[CH];
    int g = blockIdx.x;
    int t = threadIdx.x;
    float cntf = g_counts[g];
    int start = g_gstart[g];
    int cnt = (int)cntf;
    float s = 0.0f;
    for (int i = 0; i < cnt; i++)
        s += __half2float(g_agg[(size_t)(start + i) * CH + t]);
    p[t] = s / fmaxf(cntf, 1.0f);
    if (t < RDIM) rv[t] = rst[g * RDIM + t];
    __syncthreads();
    if (t < 64) {
        float a = bg[t];
#pragma unroll 4
        for (int k = 0; k < 128; k++) a = fmaf(p[k], Wg[k * 64 + t], a);
        comb[t] = fmaxf(a, 0.0f);
    } else {
        int j = t - 64;
        float a = br[j];
#pragma unroll 4
        for (int k = 0; k < 64; k++) a = fmaf(rv[k], Wr[k * 64 + j], a);
        comb[64 + j] = fmaxf(a, 0.0f);
    }
    __syncthreads();
    if (t < 2) {
        float a = bc[t];
        for (int k = 0; k < 128; k++) a = fmaf(comb[k], Wc[k * 2 + t], a);
        out[g * 2 + t] = a;
    }
}

// ---------------- streams/events for fork-join overlap (created at load) ---------
static cudaStream_t s_stream2;
static cudaEvent_t  s_ev_root, s_ev_gemm1;
static struct StreamInit {
    StreamInit() {
        cudaStreamCreateWithFlags(&s_stream2, cudaStreamNonBlocking);
        cudaEventCreateWithFlags(&s_ev_root, cudaEventDisableTiming);
        cudaEventCreateWithFlags(&s_ev_gemm1, cudaEventDisableTiming);
    }
} s_streaminit;

// ---------------- launcher ----------------
extern "C" void kernel_launch(void* const* d_in, const int* in_sizes, int n_in,
                              void* d_out, int out_size) {
    const float* x     = (const float*)d_in[0];
    const void*  ei    = d_in[1];
    const void*  batch = d_in[2];
    const float* rst   = (const float*)d_in[3];
    int base = (n_in >= 17) ? 5 : 4;
    const float* W1    = (const float*)d_in[base + 0];
    const float* b1    = (const float*)d_in[base + 1];
    const float* gamma = (const float*)d_in[base + 2];
    const float* beta  = (const float*)d_in[base + 3];
    const float* W2    = (const float*)d_in[base + 4];
    const float* b2    = (const float*)d_in[base + 5];
    const float* Wg    = (const float*)d_in[base + 6];
    const float* bg    = (const float*)d_in[base + 7];
    const float* Wr    = (const float*)d_in[base + 8];
    const float* br    = (const float*)d_in[base + 9];
    const float* Wc    = (const float*)d_in[base + 10];
    const float* bc    = (const float*)d_in[base + 11];
    float* out = (float*)d_out;

    int nblk_nodes = (N_NODES + 255) / 256;
    int nblk_edges = (N_EDGES + 255) / 256;
    int gemm_blocks = (N_NODES + 127) / 128;          // 782
    int agg_blocks = (N_NODES * 32 + 255) / 256;      // 12500
    int bn_blocks = (N_NODES + 511) / 512;            // 196

    // fork: GEMM1 (independent of CSR build) on stream2
    cudaEventRecord(s_ev_root, 0);
    cudaStreamWaitEvent(s_stream2, s_ev_root, 0);
    gemm_tc_kernel<false><<<gemm_blocks, 256, 0, s_stream2>>>(x, W1, nullptr, nullptr);
    cudaEventRecord(s_ev_gemm1, s_stream2);

    // main stream: graph structure
    init_kernel<<<nblk_nodes, 256>>>((const int*)ei);
    deg_kernel<<<nblk_edges, 256>>>(ei, batch);
    scan1_kernel<<<NBLK, SCAN_BLK>>>();
    scan2_kernel<<<1, 512>>>();
    scatter_kernel<<<nblk_edges, 256>>>(ei);

    // join, then layer-1 aggregation
    cudaStreamWaitEvent(0, s_ev_gemm1, 0);
    agg_kernel<<<agg_blocks, 256>>>(b1);

    // BN stats (finalize fused into gemm2 prologue)
    bnstats_kernel<<<bn_blocks, 256>>>();

    // layer 2
    gemm_tc_kernel<true><<<gemm_blocks, 256>>>(nullptr, W2, gamma, beta);
    agg_kernel<<<agg_blocks, 256>>>(b2);

    // pooling + head
    final_kernel<<<NGRAPH, 128>>>(rst, Wg, bg, Wr, br, Wc, bc, out);
}